// round 1
// baseline (speedup 1.0000x reference)
#include <cuda_runtime.h>
#include <cuda_bf16.h>

// Problem constants (validated against in_sizes at launch).
#define NMAX 50000
#define EMAX 800000
#define F 128     // in/out feature dim
#define EFD 6     // edge feature dim

// ---------------- device scratch (static: no allocations allowed) ----------
__device__ int   g_is64;
__device__ int   g_counts[NMAX];
__device__ int   g_cursor[NMAX];
__device__ int   g_rowptr[NMAX + 1];
__device__ int   g_src[EMAX];
__device__ int   g_dst[EMAX];
__device__ int2  g_edges[EMAX];          // (src, edge-id) sorted by dst
__device__ float4 g_aggX[NMAX * (F / 4)]; // sum of X[src] per node (25.6 MB)
__device__ float  g_aggE[NMAX * EFD];     // sum of edgeFeatures per node

// ---------------- K0: zero counts + detect index width ---------------------
__global__ void k0_zero_detect(const void* __restrict__ ei, int N, int E) {
    int i = blockIdx.x * blockDim.x + threadIdx.x;
    if (i < N) g_counts[i] = 0;
    if (i == 0) {
        // Interpret the first words as int64. Genuine int64 indices are all in
        // [0, N). Packed int32 pairs would need ~64 consecutive dst==0 to fool
        // this -> probability ~0.
        const long long* p = (const long long*)ei;
        int ok = 1;
        int lim = E < 128 ? E : 128;
        for (int j = 0; j < lim; j++) {
            long long v = p[j];
            if (v < 0 || v >= (long long)N) { ok = 0; break; }
        }
        g_is64 = ok;
    }
}

// ---------------- K1: decode edgeIndex + histogram of dst ------------------
__global__ void k1_decode_hist(const void* __restrict__ ei, int E) {
    int e = blockIdx.x * blockDim.x + threadIdx.x;
    if (e >= E) return;
    int s, d;
    if (g_is64) {
        const long long* p = (const long long*)ei;
        s = (int)p[2 * e];
        d = (int)p[2 * e + 1];
    } else {
        const int* p = (const int*)ei;
        s = p[2 * e];
        d = p[2 * e + 1];
    }
    g_src[e] = s;
    g_dst[e] = d;
    atomicAdd(&g_counts[d], 1);
}

// ---------------- K2: single-block exclusive scan (counts -> rowptr) -------
__global__ void k2_scan(int N) {
    __shared__ int wsum[32];
    __shared__ int sc[32];
    __shared__ int carry;
    int t = threadIdx.x, lane = t & 31, wid = t >> 5;
    if (t == 0) carry = 0;
    __syncthreads();
    for (int base = 0; base < N; base += 1024) {
        int i = base + t;
        int v = (i < N) ? g_counts[i] : 0;
        int x = v;
        #pragma unroll
        for (int o = 1; o < 32; o <<= 1) {
            int y = __shfl_up_sync(0xffffffffu, x, o);
            if (lane >= o) x += y;
        }
        if (lane == 31) wsum[wid] = x;
        __syncthreads();
        if (wid == 0) {
            int xx = wsum[lane];
            #pragma unroll
            for (int o = 1; o < 32; o <<= 1) {
                int y = __shfl_up_sync(0xffffffffu, xx, o);
                if (lane >= o) xx += y;
            }
            sc[lane] = xx;
        }
        __syncthreads();
        int excl = x - v + (wid > 0 ? sc[wid - 1] : 0) + carry;
        if (i < N) { g_rowptr[i] = excl; g_cursor[i] = excl; }
        int total = sc[31];
        __syncthreads();
        if (t == 0) carry += total;
        __syncthreads();
    }
    if (t == 0) g_rowptr[N] = carry;
}

// ---------------- K3: scatter edges into CSR slots --------------------------
__global__ void k3_scatter(int E) {
    int e = blockIdx.x * blockDim.x + threadIdx.x;
    if (e >= E) return;
    int d = g_dst[e];
    int p = atomicAdd(&g_cursor[d], 1);
    g_edges[p] = make_int2(g_src[e], e);
}

// ---------------- K4: warp-per-node aggregation (no float atomics) ---------
__global__ void k4_aggregate(const float4* __restrict__ X4,
                             const float* __restrict__ eF, int N) {
    int gwarp = (blockIdx.x * blockDim.x + threadIdx.x) >> 5;
    int lane  = threadIdx.x & 31;
    int nwarp = (gridDim.x * blockDim.x) >> 5;
    for (int v = gwarp; v < N; v += nwarp) {
        int s0 = g_rowptr[v], s1 = g_rowptr[v + 1];
        float4 acc = make_float4(0.f, 0.f, 0.f, 0.f);
        float ae = 0.f;
        for (int i = s0; i < s1; i++) {
            int2 se = g_edges[i];                 // broadcast load
            float4 xv = X4[(long)se.x * 32 + lane]; // gather X[src], L2-resident
            acc.x += xv.x; acc.y += xv.y; acc.z += xv.z; acc.w += xv.w;
            if (lane < EFD) ae += eF[(long)se.y * EFD + lane];
        }
        g_aggX[(long)v * 32 + lane] = acc;
        if (lane < EFD) g_aggE[v * EFD + lane] = ae;
    }
}

// ---------------- K5: fused GEMM + edge-GEMM + bias*deg + relu -------------
// Dyn smem: Ws[128*128] | Wes[6*128] | bsum[128] | xs[16 warps][8 rows][32 f4]
#define K5_THREADS 512
#define K5_RPW 8
#define K5_SMEM ((F*F + EFD*F + F) * 4 + (K5_THREADS/32) * K5_RPW * F * 4)

__global__ __launch_bounds__(K5_THREADS)
void k5_final(const float* __restrict__ W, const float* __restrict__ b,
              const float* __restrict__ We, const float* __restrict__ be,
              float* __restrict__ out, int N) {
    extern __shared__ float smem[];
    float*  Ws   = smem;               // 16384
    float*  Wes  = Ws + F * F;         // 768
    float*  bsum = Wes + EFD * F;      // 128
    float4* xs   = (float4*)(bsum + F);

    int tid = threadIdx.x;
    for (int i = tid; i < F * F; i += K5_THREADS) Ws[i] = W[i];
    for (int i = tid; i < EFD * F; i += K5_THREADS) Wes[i] = We[i];
    for (int i = tid; i < F; i += K5_THREADS) bsum[i] = b[i] + be[i];
    __syncthreads();

    int warp = tid >> 5, lane = tid & 31;
    float4* xw4 = xs + warp * (K5_RPW * 32);
    const float* xw = (const float*)xw4;

    int nGroups = (N + K5_RPW - 1) / K5_RPW;
    for (int g = blockIdx.x * (K5_THREADS / 32) + warp; g < nGroups;
         g += gridDim.x * (K5_THREADS / 32)) {
        int row0 = g * K5_RPW;
        int nr = N - row0; if (nr > K5_RPW) nr = K5_RPW;
        // stage 8 rows of aggX into this warp's smem slice
        #pragma unroll
        for (int r = 0; r < K5_RPW; r++) {
            int row = row0 + (r < nr ? r : 0);
            xw4[r * 32 + lane] = g_aggX[(long)row * 32 + lane];
        }
        __syncwarp();

        float4 acc[K5_RPW];
        #pragma unroll
        for (int r = 0; r < K5_RPW; r++) acc[r] = make_float4(0.f, 0.f, 0.f, 0.f);

        #pragma unroll 4
        for (int k = 0; k < F; k++) {
            float4 w4 = ((const float4*)(Ws + (k << 7)))[lane];
            #pragma unroll
            for (int r = 0; r < K5_RPW; r++) {
                float xk = xw[(r << 7) + k];
                acc[r].x = fmaf(xk, w4.x, acc[r].x);
                acc[r].y = fmaf(xk, w4.y, acc[r].y);
                acc[r].z = fmaf(xk, w4.z, acc[r].z);
                acc[r].w = fmaf(xk, w4.w, acc[r].w);
            }
        }

        float4 b4 = ((const float4*)bsum)[lane];
        for (int r = 0; r < nr; r++) {
            int row = row0 + r;
            float deg = (float)(g_rowptr[row + 1] - g_rowptr[row]);
            float4 o = acc[r];
            o.x = fmaf(deg, b4.x, o.x);
            o.y = fmaf(deg, b4.y, o.y);
            o.z = fmaf(deg, b4.z, o.z);
            o.w = fmaf(deg, b4.w, o.w);
            #pragma unroll
            for (int k = 0; k < EFD; k++) {
                float ek = g_aggE[row * EFD + k];
                float4 w4 = ((const float4*)(Wes + (k << 7)))[lane];
                o.x = fmaf(ek, w4.x, o.x);
                o.y = fmaf(ek, w4.y, o.y);
                o.z = fmaf(ek, w4.z, o.z);
                o.w = fmaf(ek, w4.w, o.w);
            }
            o.x = fmaxf(o.x, 0.f); o.y = fmaxf(o.y, 0.f);
            o.z = fmaxf(o.z, 0.f); o.w = fmaxf(o.w, 0.f);
            ((float4*)out)[(long)row * 32 + lane] = o;
        }
        __syncwarp();
    }
}

// ---------------------------------------------------------------------------
extern "C" void kernel_launch(void* const* d_in, const int* in_sizes, int n_in,
                              void* d_out, int out_size) {
    const float* X  = (const float*)d_in[0];
    const void*  EI = d_in[1];
    const float* EF = (const float*)d_in[2];
    const float* W  = (const float*)d_in[3];
    const float* b  = (const float*)d_in[4];
    const float* We = (const float*)d_in[5];
    const float* be = (const float*)d_in[6];
    float* out = (float*)d_out;

    int N = in_sizes[0] / F;             // 50000
    int E = in_sizes[2] / EFD;           // 800000 (edgeFeatures: dtype-unambiguous)

    cudaFuncSetAttribute(k5_final, cudaFuncAttributeMaxDynamicSharedMemorySize,
                         K5_SMEM);

    k0_zero_detect<<<(N + 255) / 256, 256>>>(EI, N, E);
    k1_decode_hist<<<(E + 255) / 256, 256>>>(EI, E);
    k2_scan<<<1, 1024>>>(N);
    k3_scatter<<<(E + 255) / 256, 256>>>(E);
    k4_aggregate<<<(N * 32 + 255) / 256, 256>>>((const float4*)X, EF, N);
    k5_final<<<148, K5_THREADS, K5_SMEM>>>(W, b, We, be, out, N);
}

// round 2
// speedup vs baseline: 1.2014x; 1.2014x over previous
#include <cuda_runtime.h>
#include <cuda_bf16.h>

#define NMAX 50000
#define EMAX 800000
#define F 128
#define EFD 6
#define SCAN_T 256

// ---------------- device scratch ----------------
__device__ int   g_is64;
__device__ int   g_counts[NMAX];
__device__ int   g_cursor[NMAX];
__device__ int   g_rowptr[NMAX + 1];
__device__ int   g_src[EMAX];
__device__ int   g_dst[EMAX];
__device__ int2  g_edges[EMAX];
__device__ float4 g_aggX[NMAX * (F / 4)];
__device__ float  g_aggE[NMAX * EFD];
__device__ int   g_blocksum[SCAN_T];
__device__ int   g_blockoff[SCAN_T];

// ---------------- K0: zero counts + detect index width ---------------------
__global__ void k0_zero_detect(const void* __restrict__ ei, int N, int E) {
    int i = blockIdx.x * blockDim.x + threadIdx.x;
    if (i < N) g_counts[i] = 0;
    if (i == 0) {
        const long long* p = (const long long*)ei;
        int ok = 1;
        int lim = E < 128 ? E : 128;
        for (int j = 0; j < lim; j++) {
            long long v = p[j];
            if (v < 0 || v >= (long long)N) { ok = 0; break; }
        }
        g_is64 = ok;
    }
}

// ---------------- K1: decode edgeIndex + histogram of dst ------------------
__global__ void k1_decode_hist(const void* __restrict__ ei, int E) {
    int e = blockIdx.x * blockDim.x + threadIdx.x;
    if (e >= E) return;
    int s, d;
    if (g_is64) {
        const long long* p = (const long long*)ei;
        s = (int)p[2 * e];
        d = (int)p[2 * e + 1];
    } else {
        const int* p = (const int*)ei;
        s = p[2 * e];
        d = p[2 * e + 1];
    }
    g_src[e] = s;
    g_dst[e] = d;
    atomicAdd(&g_counts[d], 1);
}

// ---------------- K2a/b/c: multi-block exclusive scan ------------------------
__device__ __forceinline__ int block_scan_256(int v, int* ws) {
    // returns inclusive scan of v across 256 threads; ws[8] shared; ws[7]=total
    int t = threadIdx.x, lane = t & 31, wid = t >> 5;
    int x = v;
    #pragma unroll
    for (int o = 1; o < 32; o <<= 1) {
        int y = __shfl_up_sync(0xffffffffu, x, o);
        if (lane >= o) x += y;
    }
    if (lane == 31) ws[wid] = x;
    __syncthreads();
    if (wid == 0 && lane < 8) {
        int y = ws[lane];
        #pragma unroll
        for (int o = 1; o < 8; o <<= 1) {
            int z = __shfl_up_sync(0x000000ffu, y, o);
            if (lane >= o) y += z;
        }
        ws[lane] = y;
    }
    __syncthreads();
    return x + (wid > 0 ? ws[wid - 1] : 0);
}

__global__ void k2a_tile_scan(int N) {
    __shared__ int ws[8];
    int i = blockIdx.x * SCAN_T + threadIdx.x;
    int v = (i < N) ? g_counts[i] : 0;
    int incl = block_scan_256(v, ws);
    if (i < N) g_rowptr[i] = incl - v;     // local exclusive
    if (threadIdx.x == 0) g_blocksum[blockIdx.x] = ws[7];
}

__global__ void k2b_blocksum_scan(int B, int N) {
    __shared__ int ws[8];
    int t = threadIdx.x;
    int v = (t < B) ? g_blocksum[t] : 0;
    int incl = block_scan_256(v, ws);
    if (t < B) g_blockoff[t] = incl - v;   // exclusive
    if (t == 0) g_rowptr[N] = ws[7];       // total edges
}

__global__ void k2c_add_offsets(int N) {
    int i = blockIdx.x * blockDim.x + threadIdx.x;
    if (i < N) {
        int r = g_rowptr[i] + g_blockoff[i >> 8];
        g_rowptr[i] = r;
        g_cursor[i] = r;
    }
}

// ---------------- K3: scatter edges into CSR slots (MLP=4) ------------------
__global__ void k3_scatter(int E) {
    int e0 = (blockIdx.x * blockDim.x + threadIdx.x) * 4;
    int d[4], s[4];
    #pragma unroll
    for (int j = 0; j < 4; j++) {
        int e = e0 + j;
        if (e < E) { d[j] = g_dst[e]; s[j] = g_src[e]; }
    }
    #pragma unroll
    for (int j = 0; j < 4; j++) {
        int e = e0 + j;
        if (e < E) {
            int p = atomicAdd(&g_cursor[d[j]], 1);
            g_edges[p] = make_int2(s[j], e);
        }
    }
}

// ---------------- K4: warp-per-node aggregation, chunked gather -------------
__global__ void k4_aggregate(const float4* __restrict__ X4,
                             const float* __restrict__ eF, int N) {
    int gwarp = (blockIdx.x * blockDim.x + threadIdx.x) >> 5;
    int lane  = threadIdx.x & 31;
    int nwarp = (gridDim.x * blockDim.x) >> 5;
    for (int v = gwarp; v < N; v += nwarp) {
        int s0 = g_rowptr[v], s1 = g_rowptr[v + 1];
        float4 acc = make_float4(0.f, 0.f, 0.f, 0.f);
        float ae = 0.f;
        for (int base = s0; base < s1; base += 32) {
            int cnt = s1 - base; if (cnt > 32) cnt = 32;
            // coalesced chunk load of up to 32 edges
            int2 se = g_edges[base + (lane < cnt ? lane : 0)];
            for (int j = 0; j < cnt; j += 4) {
                #pragma unroll
                for (int u = 0; u < 4; u++) {
                    if (j + u < cnt) {  // uniform across warp
                        int sj = __shfl_sync(0xffffffffu, se.x, j + u);
                        int ej = __shfl_sync(0xffffffffu, se.y, j + u);
                        float4 xv = X4[(long)sj * 32 + lane];
                        acc.x += xv.x; acc.y += xv.y;
                        acc.z += xv.z; acc.w += xv.w;
                        if (lane < EFD) ae += eF[(long)ej * EFD + lane];
                    }
                }
            }
        }
        g_aggX[(long)v * 32 + lane] = acc;
        if (lane < EFD) g_aggE[v * EFD + lane] = ae;
    }
}

// ---------------- K5: fused GEMM + edge-GEMM + bias*deg + relu -------------
#define K5_THREADS 512
#define K5_RPW 8
#define K5_SMEM ((F*F + EFD*F + F) * 4 + (K5_THREADS/32) * K5_RPW * F * 4)

__global__ __launch_bounds__(K5_THREADS)
void k5_final(const float* __restrict__ W, const float* __restrict__ b,
              const float* __restrict__ We, const float* __restrict__ be,
              float* __restrict__ out, int N) {
    extern __shared__ float smem[];
    float*  Ws   = smem;
    float*  Wes  = Ws + F * F;
    float*  bsum = Wes + EFD * F;
    float4* xs   = (float4*)(bsum + F);

    int tid = threadIdx.x;
    for (int i = tid; i < F * F; i += K5_THREADS) Ws[i] = W[i];
    for (int i = tid; i < EFD * F; i += K5_THREADS) Wes[i] = We[i];
    for (int i = tid; i < F; i += K5_THREADS) bsum[i] = b[i] + be[i];
    __syncthreads();

    int warp = tid >> 5, lane = tid & 31;
    float4* xw4 = xs + warp * (K5_RPW * 32);
    const float* xw = (const float*)xw4;

    int nGroups = (N + K5_RPW - 1) / K5_RPW;
    for (int g = blockIdx.x * (K5_THREADS / 32) + warp; g < nGroups;
         g += gridDim.x * (K5_THREADS / 32)) {
        int row0 = g * K5_RPW;
        int nr = N - row0; if (nr > K5_RPW) nr = K5_RPW;
        #pragma unroll
        for (int r = 0; r < K5_RPW; r++) {
            int row = row0 + (r < nr ? r : 0);
            xw4[r * 32 + lane] = g_aggX[(long)row * 32 + lane];
        }
        __syncwarp();

        float4 acc[K5_RPW];
        #pragma unroll
        for (int r = 0; r < K5_RPW; r++) acc[r] = make_float4(0.f, 0.f, 0.f, 0.f);

        // k blocked by 4: x read as float4 broadcast (1 crossbar phase each),
        // W read as LDS.128 per lane. 24 crossbar cyc vs 32 FMA cyc per block
        // -> FMA-bound.
        #pragma unroll 2
        for (int k = 0; k < F; k += 4) {
            float4 xv[K5_RPW];
            #pragma unroll
            for (int r = 0; r < K5_RPW; r++)
                xv[r] = *(const float4*)(xw + (r << 7) + k);
            #pragma unroll
            for (int kk = 0; kk < 4; kk++) {
                float4 w4 = ((const float4*)(Ws + ((k + kk) << 7)))[lane];
                #pragma unroll
                for (int r = 0; r < K5_RPW; r++) {
                    float xk = (kk == 0) ? xv[r].x : (kk == 1) ? xv[r].y
                             : (kk == 2) ? xv[r].z : xv[r].w;
                    acc[r].x = fmaf(xk, w4.x, acc[r].x);
                    acc[r].y = fmaf(xk, w4.y, acc[r].y);
                    acc[r].z = fmaf(xk, w4.z, acc[r].z);
                    acc[r].w = fmaf(xk, w4.w, acc[r].w);
                }
            }
        }

        float4 b4 = ((const float4*)bsum)[lane];
        for (int r = 0; r < nr; r++) {
            int row = row0 + r;
            float deg = (float)(g_rowptr[row + 1] - g_rowptr[row]);
            float4 o = acc[r];
            o.x = fmaf(deg, b4.x, o.x);
            o.y = fmaf(deg, b4.y, o.y);
            o.z = fmaf(deg, b4.z, o.z);
            o.w = fmaf(deg, b4.w, o.w);
            #pragma unroll
            for (int k = 0; k < EFD; k++) {
                float ek = g_aggE[row * EFD + k];
                float4 w4 = ((const float4*)(Wes + (k << 7)))[lane];
                o.x = fmaf(ek, w4.x, o.x);
                o.y = fmaf(ek, w4.y, o.y);
                o.z = fmaf(ek, w4.z, o.z);
                o.w = fmaf(ek, w4.w, o.w);
            }
            o.x = fmaxf(o.x, 0.f); o.y = fmaxf(o.y, 0.f);
            o.z = fmaxf(o.z, 0.f); o.w = fmaxf(o.w, 0.f);
            ((float4*)out)[(long)row * 32 + lane] = o;
        }
        __syncwarp();
    }
}

// ---------------------------------------------------------------------------
extern "C" void kernel_launch(void* const* d_in, const int* in_sizes, int n_in,
                              void* d_out, int out_size) {
    const float* X  = (const float*)d_in[0];
    const void*  EI = d_in[1];
    const float* EF = (const float*)d_in[2];
    const float* W  = (const float*)d_in[3];
    const float* b  = (const float*)d_in[4];
    const float* We = (const float*)d_in[5];
    const float* be = (const float*)d_in[6];
    float* out = (float*)d_out;

    int N = in_sizes[0] / F;
    int E = in_sizes[2] / EFD;
    int B = (N + SCAN_T - 1) / SCAN_T;   // 196 <= 256

    cudaFuncSetAttribute(k5_final, cudaFuncAttributeMaxDynamicSharedMemorySize,
                         K5_SMEM);

    k0_zero_detect<<<(N + 255) / 256, 256>>>(EI, N, E);
    k1_decode_hist<<<(E + 255) / 256, 256>>>(EI, E);
    k2a_tile_scan<<<B, SCAN_T>>>(N);
    k2b_blocksum_scan<<<1, SCAN_T>>>(B, N);
    k2c_add_offsets<<<B, SCAN_T>>>(N);
    k3_scatter<<<(E + 1023) / 1024, 256>>>(E);
    k4_aggregate<<<(N * 32 + 255) / 256, 256>>>((const float4*)X, EF, N);
    k5_final<<<148, K5_THREADS, K5_SMEM>>>(W, b, We, be, out, N);
}